// round 8
// baseline (speedup 1.0000x reference)
/*
 Theory:
 Reference materializes W_edge = [65536,64,64] (1.07 GB, 137 GF GEMM), twice-read.
 But msg[e,o] = sum_k h[e,k]*P[src(e),k,o] with P[n,k,o] = sum_i x[n,i]*W3[k,i*64+o].
 N=4096 << E=65536, so computing P per node (268 MB, 8.6 GF) cuts the dominant
 GEMM 16x. b3 factors into Q[n] = x[n] @ b3.reshape(64,64), added per edge.
 Edge MLP depends only on edge_attr -> computed once, reused for DEPTH=2.
 Pipeline: counting-sort edges by src; edge MLP (layer1 scalar, layer2 fp16
 mma.m16n8k16/fp32-acc GEMM); per conv: prep (x->fp16, root term, Q), P-GEMM
 (fp16 MMA 4096x16384xk64), per-node contraction with P row staged in 64KB SMEM
 reused by ~16 edges, fp32 atomics to dst.
 Precision: fp16 in / fp32 acc -> predicted rel_err 3e-4..8e-4 (< 1e-3 gate).
 Predicted dur 400-550 us: GEMM1 ~40us, 2x P-GEMM ~120us (268MB store-bound),
 2x contract ~170us (FFMA-issue + smem-crossbar), mlp1/sort/prep ~60us.
 Next rounds: tcgen05 GEMMs, fp16 P (halve 536MB/conv traffic), TC contraction.
*/
#include <cuda_runtime.h>
#include <cuda_fp16.h>
#include <cstdint>
#include <cstddef>

#define N_NODES 4096
#define N_EDGES 65536
#define L_DIM   64
#define K_DIM   256
#define ED_DIM  6
#define P_COLS  (K_DIM*L_DIM)   /* 16384 */

/* device-global scratch (no runtime allocation allowed) */
__device__ __align__(16) __half g_h1[(size_t)N_EDGES*K_DIM];   /* 32 MB */
__device__ __align__(16) float  g_h2[(size_t)N_EDGES*K_DIM];   /* 64 MB */
__device__ __align__(16) __half g_W2h[K_DIM*K_DIM];
__device__ __align__(16) __half g_T2h[(size_t)L_DIM*P_COLS];   /* W3 permuted [i][k*64+o] */
__device__ __align__(16) float  g_P[(size_t)N_NODES*P_COLS];   /* 268 MB */
__device__ __align__(16) __half g_xh[N_NODES*L_DIM];
__device__ __align__(16) float  g_Q[N_NODES*L_DIM];
__device__ __align__(16) float  g_t1[N_NODES*L_DIM];
__device__ __align__(16) float  g_x1[N_NODES*L_DIM];
__device__ int g_cnt[N_NODES];
__device__ int g_off[N_NODES+1];
__device__ int g_cur[N_NODES];
__device__ int g_order[N_EDGES];

__device__ __forceinline__ float gelu_f(float x){
    return 0.5f*x*(1.0f+erff(x*0.70710678118654752440f));
}

/* mma helpers */
__device__ __forceinline__ void ldm_x4(uint32_t* r, const void* p){
    uint32_t a = (uint32_t)__cvta_generic_to_shared(p);
    asm volatile("ldmatrix.sync.aligned.m8n8.x4.shared.b16 {%0,%1,%2,%3},[%4];"
                 : "=r"(r[0]),"=r"(r[1]),"=r"(r[2]),"=r"(r[3]) : "r"(a));
}
__device__ __forceinline__ void ldm_x4_t(uint32_t* r, const void* p){
    uint32_t a = (uint32_t)__cvta_generic_to_shared(p);
    asm volatile("ldmatrix.sync.aligned.m8n8.x4.trans.shared.b16 {%0,%1,%2,%3},[%4];"
                 : "=r"(r[0]),"=r"(r[1]),"=r"(r[2]),"=r"(r[3]) : "r"(a));
}
__device__ __forceinline__ void mma16816(float* d, const uint32_t* a, const uint32_t* b){
    asm volatile("mma.sync.aligned.m16n8k16.row.col.f32.f16.f16.f32 "
                 "{%0,%1,%2,%3},{%4,%5,%6,%7},{%8,%9},{%0,%1,%2,%3};"
                 : "+f"(d[0]),"+f"(d[1]),"+f"(d[2]),"+f"(d[3])
                 : "r"(a[0]),"r"(a[1]),"r"(a[2]),"r"(a[3]),"r"(b[0]),"r"(b[1]));
}

/* counting sort of edges by src */
__global__ void k_zero(){
    int i = blockIdx.x*blockDim.x + threadIdx.x;
    if (i < N_NODES) g_cnt[i] = 0;
}
__global__ void k_hist(const int* __restrict__ ei){
    int e = blockIdx.x*blockDim.x + threadIdx.x;
    if (e < N_EDGES) atomicAdd(&g_cnt[ei[e]], 1);
}
__global__ void k_scan(){   /* 1024 threads, 4 elems each */
    int t = threadIdx.x;
    int b = t*4;
    int v0=g_cnt[b], v1=g_cnt[b+1], v2=g_cnt[b+2], v3=g_cnt[b+3];
    int s1=v0+v1, s2=s1+v2, s3=s2+v3;
    int lane=t&31, warp=t>>5;
    int x=s3;
    #pragma unroll
    for(int d=1;d<32;d<<=1){ int y=__shfl_up_sync(0xffffffffu,x,d); if(lane>=d) x+=y; }
    __shared__ int ws[32];
    if(lane==31) ws[warp]=x;
    __syncthreads();
    if(warp==0){
        int y=ws[lane];
        #pragma unroll
        for(int d=1;d<32;d<<=1){ int z=__shfl_up_sync(0xffffffffu,y,d); if(lane>=d) y+=z; }
        ws[lane]=y;
    }
    __syncthreads();
    int wex = (warp==0)?0:ws[warp-1];
    int ex = wex + (x - s3);
    g_off[b]=ex;        g_cur[b]=ex;
    g_off[b+1]=ex+v0;   g_cur[b+1]=ex+v0;
    g_off[b+2]=ex+s1;   g_cur[b+2]=ex+s1;
    g_off[b+3]=ex+s2;   g_cur[b+3]=ex+s2;
    if(t==1023) g_off[N_NODES]=wex+x;
}
__global__ void k_scatter(const int* __restrict__ ei){
    int e = blockIdx.x*blockDim.x + threadIdx.x;
    if (e < N_EDGES){
        int pos = atomicAdd(&g_cur[ei[e]], 1);
        g_order[pos] = e;
    }
}

/* weight conversions */
__global__ void k_w2h(const float* __restrict__ W2){
    int i = blockIdx.x*blockDim.x + threadIdx.x;
    if (i < K_DIM*K_DIM) g_W2h[i] = __float2half(W2[i]);
}
/* T2h[i][k*64+o] = W3[k][i*64+o] */
__global__ void k_t2h(const float* __restrict__ W3){
    int idx = blockIdx.x*blockDim.x + threadIdx.x;
    if (idx >= K_DIM*L_DIM*L_DIM) return;
    int k = idx >> 12;
    int i = (idx >> 6) & 63;
    int o = idx & 63;
    g_T2h[(size_t)i*P_COLS + k*L_DIM + o] = __float2half(W3[idx]);
}

/* edge MLP layer 1: h1 = gelu(ea@W1 + b1), fp16 out */
__global__ void __launch_bounds__(256) k_mlp1(const float* __restrict__ ea,
                                              const float* __restrict__ W1,
                                              const float* __restrict__ b1){
    __shared__ float W1s[ED_DIM*K_DIM];
    __shared__ float eas[16][ED_DIM];
    int t = threadIdx.x;
    for (int j=t; j<ED_DIM*K_DIM; j+=256) W1s[j] = W1[j];
    int e0 = blockIdx.x*16;
    if (t < 16*ED_DIM) eas[t/ED_DIM][t%ED_DIM] = ea[e0*ED_DIM + t];
    float bb = b1[t];
    __syncthreads();
    #pragma unroll
    for (int le=0; le<16; le++){
        float s = bb;
        #pragma unroll
        for (int d=0; d<ED_DIM; d++) s += eas[le][d]*W1s[d*K_DIM + t];
        g_h1[(size_t)(e0+le)*K_DIM + t] = __float2half(gelu_f(s));
    }
}

/* fp16 MMA GEMM, 128x128 tile, 8 warps (4x2), warp 32x64.
   EPI 0: g_h2 = gelu(g_h1 @ g_W2h + b2)   KT=256, NC=256
   EPI 1: g_P  = g_xh @ g_T2h              KT=64,  NC=16384   */
template<int EPI, int KT, int NC>
__global__ void __launch_bounds__(256) k_gemm(const float* __restrict__ b2){
    __shared__ __align__(16) __half As[128][40];
    __shared__ __align__(16) __half Bs[32][136];
    const __half* A = (EPI==0) ? (const __half*)g_h1 : (const __half*)g_xh;
    const __half* B = (EPI==0) ? (const __half*)g_W2h : (const __half*)g_T2h;
    float*        C = (EPI==0) ? g_h2 : g_P;
    int bm = blockIdx.x, bn = blockIdx.y;
    int t = threadIdx.x, lane = t&31, wid = t>>5;
    int wm = wid & 3, wn = wid >> 2;
    float acc[2][8][4];
    #pragma unroll
    for (int mi=0;mi<2;mi++)
        #pragma unroll
        for (int nj=0;nj<8;nj++){
            acc[mi][nj][0]=0.f; acc[mi][nj][1]=0.f; acc[mi][nj][2]=0.f; acc[mi][nj][3]=0.f;
        }

    for (int kt=0; kt<KT/32; kt++){
        #pragma unroll
        for (int p=0;p<2;p++){
            int idx=t+p*256;
            int r=idx>>2, c=(idx&3)*8;
            *(uint4*)(&As[r][c]) = *(const uint4*)(A + (size_t)(bm*128+r)*KT + kt*32 + c);
        }
        #pragma unroll
        for (int p=0;p<2;p++){
            int idx=t+p*256;
            int r=idx>>4, c=(idx&15)*8;
            *(uint4*)(&Bs[r][c]) = *(const uint4*)(B + (size_t)(kt*32+r)*NC + bn*128 + c);
        }
        __syncthreads();
        #pragma unroll
        for (int k16=0;k16<2;k16++){
            uint32_t af[2][4];
            #pragma unroll
            for (int mi=0;mi<2;mi++)
                ldm_x4(af[mi], &As[wm*32 + mi*16 + (lane&15)][k16*16 + (lane>>4)*8]);
            uint32_t bf[8][2];
            #pragma unroll
            for (int np=0;np<4;np++){
                uint32_t r4[4];
                ldm_x4_t(r4, &Bs[k16*16 + ((lane>>3)&1)*8 + (lane&7)]
                               [wn*64 + np*16 + (lane>>4)*8]);
                bf[np*2  ][0]=r4[0]; bf[np*2  ][1]=r4[1];
                bf[np*2+1][0]=r4[2]; bf[np*2+1][1]=r4[3];
            }
            #pragma unroll
            for (int mi=0;mi<2;mi++)
                #pragma unroll
                for (int nj=0;nj<8;nj++)
                    mma16816(acc[mi][nj], af[mi], bf[nj]);
        }
        __syncthreads();
    }
    int row0 = bm*128 + wm*32 + (lane>>2);
    int col0 = bn*128 + wn*64 + (lane&3)*2;
    #pragma unroll
    for (int mi=0;mi<2;mi++){
        #pragma unroll
        for (int nj=0;nj<8;nj++){
            int r = row0 + mi*16, c = col0 + nj*8;
            float v0=acc[mi][nj][0], v1=acc[mi][nj][1], v2=acc[mi][nj][2], v3=acc[mi][nj][3];
            if (EPI==0){
                float bc0=b2[c], bc1=b2[c+1];
                v0=gelu_f(v0+bc0); v1=gelu_f(v1+bc1);
                v2=gelu_f(v2+bc0); v3=gelu_f(v3+bc1);
            }
            C[(size_t)r*NC + c]       = v0;
            C[(size_t)r*NC + c + 1]   = v1;
            C[(size_t)(r+8)*NC + c]   = v2;
            C[(size_t)(r+8)*NC + c+1] = v3;
        }
    }
}

/* per-conv prep: xh = half(x); R = x@Wroot + bias; Q = x@b3r.
   conv==0: x = nodes (ext), R -> g_t1 ; conv==1: x = g_x1, R -> out (ext) */
__global__ void k_prep(int conv, const float* __restrict__ x_ext,
                       const float* __restrict__ Wr, const float* __restrict__ bias,
                       const float* __restrict__ b3, float* __restrict__ R_ext){
    __shared__ float xs[L_DIM];
    int n = blockIdx.x, o = threadIdx.x;
    const float* x = (conv==0) ? x_ext : g_x1;
    float* R = (conv==0) ? g_t1 : R_ext;
    xs[o] = x[n*L_DIM + o];
    __syncthreads();
    g_xh[n*L_DIM + o] = __float2half(xs[o]);
    float r = bias[o], q = 0.f;
    #pragma unroll
    for (int i=0;i<L_DIM;i++){
        float xv = xs[i];
        r += xv*Wr[i*L_DIM + o];
        q += xv*b3[i*L_DIM + o];
    }
    R[n*L_DIM + o] = r;
    g_Q[n*L_DIM + o] = q;
}

/* contraction: per src node n, msg[e] = h2[e] @ P[n] + Q[n]; atomicAdd into dst rows */
__global__ void __launch_bounds__(256) k_contract(int conv, const int* __restrict__ ei,
                                                  float* __restrict__ out_ext){
    extern __shared__ float sm[];
    float* Ps = sm;                 /* 16384 floats */
    float* hs = sm + 16384;         /* 16*260 */
    float* Qs = hs + 16*260;        /* 64 */
    float* target = (conv==0) ? g_t1 : out_ext;

    int n = blockIdx.x;
    int beg = g_off[n], end = g_off[n+1];
    if (beg == end) return;
    int t = threadIdx.x;

    const float4* p4 = (const float4*)(g_P + (size_t)n*P_COLS);
    float4* Ps4 = (float4*)Ps;
    #pragma unroll
    for (int j=0;j<16;j++) Ps4[t + j*256] = p4[t + j*256];
    if (t < 64) Qs[t] = g_Q[n*L_DIM + t];

    for (int gb = beg; gb < end; gb += 16){
        int ne = min(16, end - gb);
        __syncthreads();   /* P/Q ready (first iter); hs free (later iters) */
        for (int j = t; j < ne*64; j += 256){
            int le = j>>6, c4 = j&63;
            int e = g_order[gb+le];
            float4 v = ((const float4*)(g_h2 + (size_t)e*K_DIM))[c4];
            *(float4*)&hs[le*260 + c4*4] = v;
        }
        __syncthreads();
        int le = t>>4;
        int og = t&15;
        if (le < ne){
            const float4* he4 = (const float4*)(hs + le*260);
            float ax=0.f, ay=0.f, az=0.f, aw=0.f;
            #pragma unroll 8
            for (int k4=0; k4<64; k4++){
                float4 hv = he4[k4];
                float4 p0 = Ps4[(k4*4+0)*16 + og];
                float4 p1 = Ps4[(k4*4+1)*16 + og];
                float4 p2 = Ps4[(k4*4+2)*16 + og];
                float4 p3 = Ps4[(k4*4+3)*16 + og];
                ax += hv.x*p0.x + hv.y*p1.x + hv.z*p2.x + hv.w*p3.x;
                ay += hv.x*p0.y + hv.y*p1.y + hv.z*p2.y + hv.w*p3.y;
                az += hv.x*p0.z + hv.y*p1.z + hv.z*p2.z + hv.w*p3.z;
                aw += hv.x*p0.w + hv.y*p1.w + hv.z*p2.w + hv.w*p3.w;
            }
            int e = g_order[gb+le];
            int dst = ei[N_EDGES + e];
            int o = og*4;
            float* tg = target + (size_t)dst*L_DIM + o;
            atomicAdd(tg+0, ax + Qs[o]);
            atomicAdd(tg+1, ay + Qs[o+1]);
            atomicAdd(tg+2, az + Qs[o+2]);
            atomicAdd(tg+3, aw + Qs[o+3]);
        }
    }
}

__global__ void k_gelu_mid(){
    int i = blockIdx.x*blockDim.x + threadIdx.x;
    if (i < N_NODES*L_DIM) g_x1[i] = gelu_f(g_t1[i]);
}

extern "C" void kernel_launch(void* const* d_in, const int* in_sizes, int n_in,
                              void* d_out, int out_size){
    const float* nodes = (const float*)d_in[0];
    const int*   ei    = (const int*)  d_in[1];
    const float* ea    = (const float*)d_in[2];
    const float* W1    = (const float*)d_in[3];
    const float* b1    = (const float*)d_in[4];
    const float* W2    = (const float*)d_in[5];
    const float* b2    = (const float*)d_in[6];
    const float* W3    = (const float*)d_in[7];
    const float* b3    = (const float*)d_in[8];
    const float* Wr    = (const float*)d_in[9];
    const float* bias  = (const float*)d_in[10];
    float* out = (float*)d_out;
    (void)in_sizes; (void)n_in; (void)out_size;

    const int SMEM_CONTRACT = (16384 + 16*260 + 64) * 4;   /* 70400 B */
    cudaFuncSetAttribute(k_contract, cudaFuncAttributeMaxDynamicSharedMemorySize, SMEM_CONTRACT);

    /* sort edges by src */
    k_zero<<<16,256>>>();
    k_hist<<<256,256>>>(ei);
    k_scan<<<1,1024>>>();
    k_scatter<<<256,256>>>(ei);

    /* weight converts */
    k_w2h<<<256,256>>>(W2);
    k_t2h<<<4096,256>>>(W3);

    /* edge MLP (once; reused across both convs) */
    k_mlp1<<<N_EDGES/16,256>>>(ea, W1, b1);
    k_gemm<0,K_DIM,K_DIM><<<dim3(N_EDGES/128, K_DIM/128), 256>>>(b2);

    /* conv 1 */
    k_prep<<<N_NODES,L_DIM>>>(0, nodes, Wr, bias, b3, out);
    k_gemm<1,L_DIM,P_COLS><<<dim3(N_NODES/128, P_COLS/128), 256>>>(b2);
    k_contract<<<N_NODES,256,SMEM_CONTRACT>>>(0, ei, out);
    k_gelu_mid<<<(N_NODES*L_DIM)/256,256>>>();

    /* conv 2 */
    k_prep<<<N_NODES,L_DIM>>>(1, nodes, Wr, bias, b3, out);
    k_gemm<1,L_DIM,P_COLS><<<dim3(N_NODES/128, P_COLS/128), 256>>>(b2);
    k_contract<<<N_NODES,256,SMEM_CONTRACT>>>(1, ei, out);
}

// round 11
// speedup vs baseline: 1.7835x; 1.7835x over previous
/*
 R9 theory.
 R8 passed at 633us. Cost model of R8 says the contraction kernel dominates:
 per node it streams ~1.3 MB through the SMEM crossbar (each of 256 threads
 reads 5x LDS.128 per k4-iter with no broadcast) -> ~42M SM-cycles/conv
 (~155us/conv), plus P traffic in fp32 (268 MB store + 268 MB read per conv
 ~ 90us/conv at ~6TB/s).
 Changes this round:
  1. Contraction on tensor cores: msg[16edges,64] = h[16,256] @ P[256,64] as
     m16n8k16 fp16 MMA (8 warps = 8 n-slices). SMEM traffic per group drops
     from ~1.3MB to ~40KB of ldmatrix (30x less); compute moves to HMMA.
  2. P stored fp16 (134 MB instead of 268 MB): halves P-GEMM store and
     contract read traffic. h2 stored fp16 (32 MB) - also required as the
     MMA A-operand.
 Precision: two new fp16 quantization sources (P, h2) on top of existing
 (h1, xh, T2h). Errors roughly independent -> rel_err ~ sqrt(3.45^2+3^2+3^2)
 e-4 ~ 5.5e-4, still under the 1e-3 gate. If this fails, revert P to fp32.
 Predicted: dur 633 -> ~250-300 us (contract ~45us/conv: bound by 134MB P
 read + 4.2M float atomics; P-GEMM ~25us/conv; GEMM1 ~40us; sort/misc ~40us).
 rel_err ~5-7e-4.
 Next rounds if this lands: tcgen05/UTCHMMA for GEMM1+P-GEMM, pipelined
 cp.async GEMM stages, merge prep/gelu into neighbors.
*/
#include <cuda_runtime.h>
#include <cuda_fp16.h>
#include <cstdint>
#include <cstddef>

#define N_NODES 4096
#define N_EDGES 65536
#define L_DIM   64
#define K_DIM   256
#define ED_DIM  6
#define P_COLS  (K_DIM*L_DIM)   /* 16384 */

/* device-global scratch (no runtime allocation allowed) */
__device__ __align__(16) __half g_h1[(size_t)N_EDGES*K_DIM];    /* 32 MB */
__device__ __align__(16) __half g_h2h[(size_t)N_EDGES*K_DIM];   /* 32 MB gelu(mlp2) fp16 */
__device__ __align__(16) __half g_W2h[K_DIM*K_DIM];
__device__ __align__(16) __half g_T2h[(size_t)L_DIM*P_COLS];    /* W3 permuted [i][k*64+o] */
__device__ __align__(16) __half g_Ph[(size_t)N_NODES*P_COLS];   /* 134 MB per-node P fp16 */
__device__ __align__(16) __half g_xh[N_NODES*L_DIM];
__device__ __align__(16) float  g_Q[N_NODES*L_DIM];
__device__ __align__(16) float  g_t1[N_NODES*L_DIM];
__device__ __align__(16) float  g_x1[N_NODES*L_DIM];
__device__ int g_cnt[N_NODES];
__device__ int g_off[N_NODES+1];
__device__ int g_cur[N_NODES];
__device__ int g_order[N_EDGES];

__device__ __forceinline__ float gelu_f(float x){
    return 0.5f*x*(1.0f+erff(x*0.70710678118654752440f));
}

/* mma helpers */
__device__ __forceinline__ void ldm_x4(uint32_t* r, const void* p){
    uint32_t a = (uint32_t)__cvta_generic_to_shared(p);
    asm volatile("ldmatrix.sync.aligned.m8n8.x4.shared.b16 {%0,%1,%2,%3},[%4];"
                 : "=r"(r[0]),"=r"(r[1]),"=r"(r[2]),"=r"(r[3]) : "r"(a));
}
__device__ __forceinline__ void ldm_x4_t(uint32_t* r, const void* p){
    uint32_t a = (uint32_t)__cvta_generic_to_shared(p);
    asm volatile("ldmatrix.sync.aligned.m8n8.x4.trans.shared.b16 {%0,%1,%2,%3},[%4];"
                 : "=r"(r[0]),"=r"(r[1]),"=r"(r[2]),"=r"(r[3]) : "r"(a));
}
__device__ __forceinline__ void ldm_x2_t(uint32_t* r, const void* p){
    uint32_t a = (uint32_t)__cvta_generic_to_shared(p);
    asm volatile("ldmatrix.sync.aligned.m8n8.x2.trans.shared.b16 {%0,%1},[%2];"
                 : "=r"(r[0]),"=r"(r[1]) : "r"(a));
}
__device__ __forceinline__ void mma16816(float* d, const uint32_t* a, const uint32_t* b){
    asm volatile("mma.sync.aligned.m16n8k16.row.col.f32.f16.f16.f32 "
                 "{%0,%1,%2,%3},{%4,%5,%6,%7},{%8,%9},{%0,%1,%2,%3};"
                 : "+f"(d[0]),"+f"(d[1]),"+f"(d[2]),"+f"(d[3])
                 : "r"(a[0]),"r"(a[1]),"r"(a[2]),"r"(a[3]),"r"(b[0]),"r"(b[1]));
}

/* counting sort of edges by src */
__global__ void k_zero(){
    int i = blockIdx.x*blockDim.x + threadIdx.x;
    if (i < N_NODES) g_cnt[i] = 0;
}
__global__ void k_hist(const int* __restrict__ ei){
    int e = blockIdx.x*blockDim.x + threadIdx.x;
    if (e < N_EDGES) atomicAdd(&g_cnt[ei[e]], 1);
}
__global__ void k_scan(){   /* 1024 threads, 4 elems each */
    int t = threadIdx.x;
    int b = t*4;
    int v0=g_cnt[b], v1=g_cnt[b+1], v2=g_cnt[b+2], v3=g_cnt[b+3];
    int s1=v0+v1, s2=s1+v2, s3=s2+v3;
    int lane=t&31, warp=t>>5;
    int x=s3;
    #pragma unroll
    for(int d=1;d<32;d<<=1){ int y=__shfl_up_sync(0xffffffffu,x,d); if(lane>=d) x+=y; }
    __shared__ int ws[32];
    if(lane==31) ws[warp]=x;
    __syncthreads();
    if(warp==0){
        int y=ws[lane];
        #pragma unroll
        for(int d=1;d<32;d<<=1){ int z=__shfl_up_sync(0xffffffffu,y,d); if(lane>=d) y+=z; }
        ws[lane]=y;
    }
    __syncthreads();
    int wex = (warp==0)?0:ws[warp-1];
    int ex = wex + (x - s3);
    g_off[b]=ex;        g_cur[b]=ex;
    g_off[b+1]=ex+v0;   g_cur[b+1]=ex+v0;
    g_off[b+2]=ex+s1;   g_cur[b+2]=ex+s1;
    g_off[b+3]=ex+s2;   g_cur[b+3]=ex+s2;
    if(t==1023) g_off[N_NODES]=wex+x;
}
__global__ void k_scatter(const int* __restrict__ ei){
    int e = blockIdx.x*blockDim.x + threadIdx.x;
    if (e < N_EDGES){
        int pos = atomicAdd(&g_cur[ei[e]], 1);
        g_order[pos] = e;
    }
}

/* weight conversions */
__global__ void k_w2h(const float* __restrict__ W2){
    int i = blockIdx.x*blockDim.x + threadIdx.x;
    if (i < K_DIM*K_DIM) g_W2h[i] = __float2half(W2[i]);
}
/* T2h[i][k*64+o] = W3[k][i*64+o] */
__global__ void k_t2h(const float* __restrict__ W3){
    int idx = blockIdx.x*blockDim.x + threadIdx.x;
    if (idx >= K_DIM*L_DIM*L_DIM) return;
    int k = idx >> 12;
    int i = (idx >> 6) & 63;
    int o = idx & 63;
    g_T2h[(size_t)i*P_COLS + k*L_DIM + o] = __float2half(W3[idx]);
}

/* edge MLP layer 1: h1 = gelu(ea@W1 + b1), fp16 out */
__global__ void __launch_bounds__(256) k_mlp1(const float* __restrict__ ea,
                                              const float* __restrict__ W1,
                                              const float* __restrict__ b1){
    __shared__ float W1s[ED_DIM*K_DIM];
    __shared__ float eas[16][ED_DIM];
    int t = threadIdx.x;
    for (int j=t; j<ED_DIM*K_DIM; j+=256) W1s[j] = W1[j];
    int e0 = blockIdx.x*16;
    if (t < 16*ED_DIM) eas[t/ED_DIM][t%ED_DIM] = ea[e0*ED_DIM + t];
    float bb = b1[t];
    __syncthreads();
    #pragma unroll
    for (int le=0; le<16; le++){
        float s = bb;
        #pragma unroll
        for (int d=0; d<ED_DIM; d++) s += eas[le][d]*W1s[d*K_DIM + t];
        g_h1[(size_t)(e0+le)*K_DIM + t] = __float2half(gelu_f(s));
    }
}

/* fp16 MMA GEMM, 128x128 tile, 8 warps (4x2), warp 32x64, fp16 output.
   EPI 0: g_h2h = gelu(g_h1 @ g_W2h + b2)   KT=256, NC=256
   EPI 1: g_Ph  = g_xh @ g_T2h              KT=64,  NC=16384   */
template<int EPI, int KT, int NC>
__global__ void __launch_bounds__(256) k_gemm(const float* __restrict__ b2){
    __shared__ __align__(16) __half As[128][40];
    __shared__ __align__(16) __half Bs[32][136];
    const __half* A = (EPI==0) ? (const __half*)g_h1 : (const __half*)g_xh;
    const __half* B = (EPI==0) ? (const __half*)g_W2h : (const __half*)g_T2h;
    __half*       C = (EPI==0) ? g_h2h : g_Ph;
    int bm = blockIdx.x, bn = blockIdx.y;
    int t = threadIdx.x, lane = t&31, wid = t>>5;
    int wm = wid & 3, wn = wid >> 2;
    float acc[2][8][4];
    #pragma unroll
    for (int mi=0;mi<2;mi++)
        #pragma unroll
        for (int nj=0;nj<8;nj++){
            acc[mi][nj][0]=0.f; acc[mi][nj][1]=0.f; acc[mi][nj][2]=0.f; acc[mi][nj][3]=0.f;
        }

    for (int kt=0; kt<KT/32; kt++){
        #pragma unroll
        for (int p=0;p<2;p++){
            int idx=t+p*256;
            int r=idx>>2, c=(idx&3)*8;
            *(uint4*)(&As[r][c]) = *(const uint4*)(A + (size_t)(bm*128+r)*KT + kt*32 + c);
        }
        #pragma unroll
        for (int p=0;p<2;p++){
            int idx=t+p*256;
            int r=idx>>4, c=(idx&15)*8;
            *(uint4*)(&Bs[r][c]) = *(const uint4*)(B + (size_t)(kt*32+r)*NC + bn*128 + c);
        }
        __syncthreads();
        #pragma unroll
        for (int k16=0;k16<2;k16++){
            uint32_t af[2][4];
            #pragma unroll
            for (int mi=0;mi<2;mi++)
                ldm_x4(af[mi], &As[wm*32 + mi*16 + (lane&15)][k16*16 + (lane>>4)*8]);
            uint32_t bf[8][2];
            #pragma unroll
            for (int np=0;np<4;np++){
                uint32_t r4[4];
                ldm_x4_t(r4, &Bs[k16*16 + ((lane>>3)&1)*8 + (lane&7)]
                               [wn*64 + np*16 + (lane>>4)*8]);
                bf[np*2  ][0]=r4[0]; bf[np*2  ][1]=r4[1];
                bf[np*2+1][0]=r4[2]; bf[np*2+1][1]=r4[3];
            }
            #pragma unroll
            for (int mi=0;mi<2;mi++)
                #pragma unroll
                for (int nj=0;nj<8;nj++)
                    mma16816(acc[mi][nj], af[mi], bf[nj]);
        }
        __syncthreads();
    }
    int row0 = bm*128 + wm*32 + (lane>>2);
    int col0 = bn*128 + wn*64 + (lane&3)*2;
    #pragma unroll
    for (int mi=0;mi<2;mi++){
        #pragma unroll
        for (int nj=0;nj<8;nj++){
            int r = row0 + mi*16, c = col0 + nj*8;
            float v0=acc[mi][nj][0], v1=acc[mi][nj][1], v2=acc[mi][nj][2], v3=acc[mi][nj][3];
            if (EPI==0){
                float bc0=b2[c], bc1=b2[c+1];
                v0=gelu_f(v0+bc0); v1=gelu_f(v1+bc1);
                v2=gelu_f(v2+bc0); v3=gelu_f(v3+bc1);
            }
            *(__half2*)(C + (size_t)r*NC + c)     = __floats2half2_rn(v0, v1);
            *(__half2*)(C + (size_t)(r+8)*NC + c) = __floats2half2_rn(v2, v3);
        }
    }
}

/* per-conv prep: xh = half(x); R = x@Wroot + bias; Q = x@b3r.
   conv==0: x = nodes (ext), R -> g_t1 ; conv==1: x = g_x1, R -> out (ext) */
__global__ void k_prep(int conv, const float* __restrict__ x_ext,
                       const float* __restrict__ Wr, const float* __restrict__ bias,
                       const float* __restrict__ b3, float* __restrict__ R_ext){
    __shared__ float xs[L_DIM];
    int n = blockIdx.x, o = threadIdx.x;
    const float* x = (conv==0) ? x_ext : g_x1;
    float* R = (conv==0) ? g_t1 : R_ext;
    xs[o] = x[n*L_DIM + o];
    __syncthreads();
    g_xh[n*L_DIM + o] = __float2half(xs[o]);
    float r = bias[o], q = 0.f;
    #pragma unroll
    for (int i=0;i<L_DIM;i++){
        float xv = xs[i];
        r += xv*Wr[i*L_DIM + o];
        q += xv*b3[i*L_DIM + o];
    }
    R[n*L_DIM + o] = r;
    g_Q[n*L_DIM + o] = q;
}

/* Tensor-core contraction: per src node n, for each group of 16 edges,
   msg[16,64] = h2[16,256] @ P[n][256,64] via m16n8k16 (8 warps = 8 n-slices),
   then atomicAdd(msg + Q) into dst rows.
   SMEM: Ps fp16 [256][72-pad] (36864B) + hs fp16 [16][264-pad] (8448B) + Qs(256B). */
#define PS_PITCH 72
#define HS_PITCH 264
__global__ void __launch_bounds__(256) k_contract(int conv, const int* __restrict__ ei,
                                                  float* __restrict__ out_ext){
    extern __shared__ __align__(16) __half smh[];
    __half* Ps = smh;                       /* 256*72 halfs */
    __half* hs = smh + 256*PS_PITCH;        /* 16*264 halfs */
    float*  Qs = (float*)(hs + 16*HS_PITCH);/* 64 floats */
    float* target = (conv==0) ? g_t1 : out_ext;

    int n = blockIdx.x;
    int beg = g_off[n], end = g_off[n+1];
    if (beg == end) return;
    int t = threadIdx.x, lane = t&31, wn = t>>5;

    /* stage P row (32KB fp16) with pitch-72 rows */
    {
        const uint4* src = (const uint4*)(g_Ph + (size_t)n*P_COLS);
        #pragma unroll
        for (int i=0;i<8;i++){
            int j = t + i*256;             /* 8-half chunk id, 0..2047 */
            int k = j>>3, o = (j&7)*8;
            *(uint4*)(Ps + k*PS_PITCH + o) = src[j];
        }
    }
    if (t < 64) Qs[t] = g_Q[n*L_DIM + t];

    for (int gb = beg; gb < end; gb += 16){
        int ne = min(16, end - gb);
        __syncthreads();   /* Ps/Qs ready (first iter); hs consumed (later iters) */
        /* stage h2 rows for this edge group, zero-pad missing rows */
        #pragma unroll
        for (int i=0;i<2;i++){
            int j = t + i*256;             /* 0..511 ; 32 chunks per edge row */
            int le = j>>5, c8 = j&31;
            uint4 v;
            if (le < ne){
                int e = g_order[gb+le];
                v = ((const uint4*)(g_h2h + (size_t)e*K_DIM))[c8];
            } else {
                v.x=0u; v.y=0u; v.z=0u; v.w=0u;
            }
            *(uint4*)(hs + le*HS_PITCH + c8*8) = v;
        }
        __syncthreads();

        float acc[4]; acc[0]=0.f; acc[1]=0.f; acc[2]=0.f; acc[3]=0.f;
        #pragma unroll
        for (int ks=0; ks<16; ks++){
            uint32_t af[4];
            ldm_x4(af, hs + (lane&15)*HS_PITCH + ks*16 + (lane>>4)*8);
            uint32_t bf[2];
            ldm_x2_t(bf, Ps + (ks*16 + (lane&15))*PS_PITCH + wn*8);
            mma16816(acc, af, bf);
        }

        int r0 = lane>>2;
        int c0 = wn*8 + (lane&3)*2;
        float q0 = Qs[c0], q1 = Qs[c0+1];
        if (r0 < ne){
            int e = g_order[gb+r0];
            int dst = ei[N_EDGES + e];
            float* tg = target + (size_t)dst*L_DIM + c0;
            atomicAdd(tg,   acc[0]+q0);
            atomicAdd(tg+1, acc[1]+q1);
        }
        if (r0+8 < ne){
            int e = g_order[gb+r0+8];
            int dst = ei[N_EDGES + e];
            float* tg = target + (size_t)dst*L_DIM + c0;
            atomicAdd(tg,   acc[2]+q0);
            atomicAdd(tg+1, acc[3]+q1);
        }
    }
}

__global__ void k_gelu_mid(){
    int i = blockIdx.x*blockDim.x + threadIdx.x;
    if (i < N_NODES*L_DIM) g_x1[i] = gelu_f(g_t1[i]);
}

extern "C" void kernel_launch(void* const* d_in, const int* in_sizes, int n_in,
                              void* d_out, int out_size){
    const float* nodes = (const float*)d_in[0];
    const int*   ei    = (const int*)  d_in[1];
    const float* ea    = (const float*)d_in[2];
    const float* W1    = (const float*)d_in[3];
    const float* b1    = (const float*)d_in[4];
    const float* W2    = (const float*)d_in[5];
    const float* b2    = (const float*)d_in[6];
    const float* W3    = (const float*)d_in[7];
    const float* b3    = (const float*)d_in[8];
    const float* Wr    = (const float*)d_in[9];
    const float* bias  = (const float*)d_in[10];
    float* out = (float*)d_out;
    (void)in_sizes; (void)n_in; (void)out_size;

    const int SMEM_CONTRACT = (256*PS_PITCH + 16*HS_PITCH)*2 + 64*4 + 16; /* ~45.6 KB */
    cudaFuncSetAttribute(k_contract, cudaFuncAttributeMaxDynamicSharedMemorySize, SMEM_CONTRACT);

    /* sort edges by src */
    k_zero<<<16,256>>>();
    k_hist<<<256,256>>>(ei);
    k_scan<<<1,1024>>>();
    k_scatter<<<256,256>>>(ei);

    /* weight converts */
    k_w2h<<<256,256>>>(W2);
    k_t2h<<<4096,256>>>(W3);

    /* edge MLP (once; reused across both convs) */
    k_mlp1<<<N_EDGES/16,256>>>(ea, W1, b1);
    k_gemm<0,K_DIM,K_DIM><<<dim3(N_EDGES/128, K_DIM/128), 256>>>(b2);

    /* conv 1 */
    k_prep<<<N_NODES,L_DIM>>>(0, nodes, Wr, bias, b3, out);
    k_gemm<1,L_DIM,P_COLS><<<dim3(N_NODES/128, P_COLS/128), 256>>>(b2);
    k_contract<<<N_NODES,256,SMEM_CONTRACT>>>(0, ei, out);
    k_gelu_mid<<<(N_NODES*L_DIM)/256,256>>>();

    /* conv 2 */
    k_prep<<<N_NODES,L_DIM>>>(1, nodes, Wr, bias, b3, out);
    k_gemm<1,L_DIM,P_COLS><<<dim3(N_NODES/128, P_COLS/128), 256>>>(b2);
    k_contract<<<N_NODES,256,SMEM_CONTRACT>>>(1, ei, out);
}